// round 10
// baseline (speedup 1.0000x reference)
#include <cuda_runtime.h>
#include <cuda_bf16.h>
#include <cstdint>
#include <math.h>

// ---------------- problem constants ----------------
#define N_TOK   4096
#define EMBED   1024
#define NHEADS  16
#define HDIM    64
#define FFN     4096
#define QKV_N   3072

// ---------------- scratch (device globals; no allocation allowed) ----------------
__device__ float g_qkv   [N_TOK * QKV_N];
__device__ float g_attn  [N_TOK * EMBED];
__device__ float g_tmp   [N_TOK * EMBED];
__device__ float g_h     [N_TOK * EMBED];
__device__ float g_ffn   [N_TOK * FFN];
__device__ float g_rfeats[N_TOK * EMBED];
__device__ float g_rwqkv [EMBED * QKV_N];
__device__ float g_rwo   [EMBED * EMBED];
__device__ float g_rw1   [EMBED * FFN];
__device__ float g_rw2   [FFN * EMBED];
__device__ int   g_seg   [N_TOK];

// ---------------- small helpers ----------------
__device__ __forceinline__ unsigned f2tf(float x) {
    unsigned r;
    asm("cvt.rna.tf32.f32 %0, %1;" : "=r"(r) : "f"(x));
    return r;
}
__device__ __forceinline__ float rtf(float x) { return __uint_as_float(f2tf(x)); }

__device__ __forceinline__ void cp16(unsigned s, const void* g) {
    asm volatile("cp.async.cg.shared.global [%0], [%1], 16;\n" :: "r"(s), "l"(g));
}
__device__ __forceinline__ float gelu_tanh(float x) {
    float x3 = x * x * x;
    return 0.5f * x * (1.0f + tanhf(0.7978845608028654f * (x + 0.044715f * x3)));
}

// ---------------- segment ids ----------------
__global__ void seg_kernel(const int* __restrict__ cu, int* __restrict__ seg) {
    int n = blockIdx.x * blockDim.x + threadIdx.x;
    if (n < N_TOK) {
        int s = 0;
        #pragma unroll
        for (int j = 1; j <= 8; j++) s += (cu[j] <= n) ? 1 : 0;
        seg[n] = s;
    }
}

// ---------------- tf32-round copy ----------------
__global__ void round_copy(const float4* __restrict__ in, float4* __restrict__ out, int n4) {
    int i = blockIdx.x * blockDim.x + threadIdx.x;
    if (i < n4) {
        float4 v = in[i];
        v.x = rtf(v.x); v.y = rtf(v.y); v.z = rtf(v.z); v.w = rtf(v.w);
        out[i] = v;
    }
}
#define RC_GRID(n4) (((n4) + 255) / 256)

// ---------------- hybrid GEMM: C[M,N] = A[M,K] @ B[K,N] + bias (opt GELU) ------
// Column tiles [0, n_mma) use tf32 mma.sync (compat tensor unit);
// tiles [n_mma, ...) use fp32 FFMA SIMT on the SAME smem pipeline.
// A, B pre-rounded to tf32 -> products exact in fp32 -> both paths agree.
#define BM 128
#define BN 128
#define BK 32
#define LDA 36    // BK + 4
#define LDB 136   // BN + 8
#define ASTG (BM * LDA * 4)             // 18432 B
#define BSTG (BK * LDB * 4)             // 17408 B
#define STG  (ASTG + BSTG)              // 35840 B
#define TG_DSMEM (2 * STG)              // 71680 B

__global__ __launch_bounds__(256) void gemm_hybrid(
    const float* __restrict__ A, const float* __restrict__ B,
    const float* __restrict__ bias, float* __restrict__ C,
    int N, int K, int act, int n_mma)
{
    extern __shared__ float smem[];
    float* sA[2] = { smem,              smem + STG / 4 };
    float* sB[2] = { smem + ASTG / 4,   smem + (STG + ASTG) / 4 };

    const int tid  = threadIdx.x;
    const int bm   = blockIdx.y * BM;
    const int bn   = blockIdx.x * BN;

    // --- shared producer mapping (cp.async, 4x16B per thread per matrix) ---
    int aoff[4], boff[4];
    const float* gA[4];
    const float* gB[4];
    #pragma unroll
    for (int i = 0; i < 4; i++) {
        int ch = tid + i * 256;
        int ar = ch >> 3, ac = ch & 7;
        aoff[i] = ar * LDA + ac * 4;
        gA[i] = A + (size_t)(bm + ar) * K + ac * 4;
        int br = ch >> 5, bc2 = ch & 31;
        boff[i] = br * LDB + bc2 * 4;
        gB[i] = B + (size_t)br * N + bn + bc2 * 4;
    }
    unsigned sAw[2][4], sBw[2][4];
    #pragma unroll
    for (int b = 0; b < 2; b++)
        #pragma unroll
        for (int i = 0; i < 4; i++) {
            sAw[b][i] = (unsigned)__cvta_generic_to_shared(sA[b] + aoff[i]);
            sBw[b][i] = (unsigned)__cvta_generic_to_shared(sB[b] + boff[i]);
        }

    const int S = K / BK;
    #pragma unroll
    for (int i = 0; i < 4; i++) { cp16(sAw[0][i], gA[i]); cp16(sBw[0][i], gB[i]); }
    asm volatile("cp.async.commit_group;\n" ::: "memory");

    if (blockIdx.x < (unsigned)n_mma) {
        // ================= tensor (mma.sync tf32) path =================
        const int lane = tid & 31;
        const int warp = tid >> 5;
        const int g    = lane >> 2;
        const int c    = lane & 3;
        const int wm   = (warp >> 2) * 64;
        const int wn   = (warp & 3) * 32;

        float acc[4][4][4] = {};

        for (int s = 0; s < S; s++) {
            asm volatile("cp.async.wait_group 0;\n" ::: "memory");
            __syncthreads();
            if (s + 1 < S) {
                int nb = (s + 1) & 1, ko = (s + 1) * BK;
                #pragma unroll
                for (int i = 0; i < 4; i++) {
                    cp16(sAw[nb][i], gA[i] + ko);
                    cp16(sBw[nb][i], gB[i] + (size_t)ko * N);
                }
                asm volatile("cp.async.commit_group;\n" ::: "memory");
            }

            const float* Ar = sA[s & 1] + (wm + g) * LDA + c;
            const float* Br = sB[s & 1] + c * LDB + wn + g;

            #pragma unroll
            for (int kk = 0; kk < 4; kk++) {
                unsigned af[4][4];
                #pragma unroll
                for (int mt = 0; mt < 4; mt++) {
                    const float* p = Ar + mt * 16 * LDA + kk * 8;
                    af[mt][0] = __float_as_uint(p[0]);
                    af[mt][1] = __float_as_uint(p[8 * LDA]);
                    af[mt][2] = __float_as_uint(p[4]);
                    af[mt][3] = __float_as_uint(p[8 * LDA + 4]);
                }
                unsigned bf[4][2];
                #pragma unroll
                for (int nt = 0; nt < 4; nt++) {
                    const float* p = Br + kk * 8 * LDB + nt * 8;
                    bf[nt][0] = __float_as_uint(p[0]);
                    bf[nt][1] = __float_as_uint(p[4 * LDB]);
                }
                #pragma unroll
                for (int mt = 0; mt < 4; mt++)
                    #pragma unroll
                    for (int nt = 0; nt < 4; nt++)
                        asm volatile(
                            "mma.sync.aligned.m16n8k8.row.col.f32.tf32.tf32.f32 "
                            "{%0,%1,%2,%3}, {%4,%5,%6,%7}, {%8,%9}, {%0,%1,%2,%3};"
                            : "+f"(acc[mt][nt][0]), "+f"(acc[mt][nt][1]),
                              "+f"(acc[mt][nt][2]), "+f"(acc[mt][nt][3])
                            : "r"(af[mt][0]), "r"(af[mt][1]), "r"(af[mt][2]), "r"(af[mt][3]),
                              "r"(bf[nt][0]), "r"(bf[nt][1]));
            }
        }

        #pragma unroll
        for (int mt = 0; mt < 4; mt++) {
            int row0 = bm + wm + mt * 16 + g;
            #pragma unroll
            for (int nt = 0; nt < 4; nt++) {
                int col = bn + wn + nt * 8 + 2 * c;
                float b0 = bias[col], b1 = bias[col + 1];
                float2 v0 = make_float2(acc[mt][nt][0] + b0, acc[mt][nt][1] + b1);
                float2 v1 = make_float2(acc[mt][nt][2] + b0, acc[mt][nt][3] + b1);
                if (act) {
                    v0.x = rtf(gelu_tanh(v0.x)); v0.y = rtf(gelu_tanh(v0.y));
                    v1.x = rtf(gelu_tanh(v1.x)); v1.y = rtf(gelu_tanh(v1.y));
                }
                *(float2*)(C + (size_t)row0 * N + col)       = v0;
                *(float2*)(C + (size_t)(row0 + 8) * N + col) = v1;
            }
        }
    } else {
        // ================= SIMT (fp32 FFMA) path =================
        const int tx = tid & 15;     // column group
        const int ty = tid >> 4;     // row group (0..15)

        float acc[8][8] = {};

        for (int s = 0; s < S; s++) {
            asm volatile("cp.async.wait_group 0;\n" ::: "memory");
            __syncthreads();
            if (s + 1 < S) {
                int nb = (s + 1) & 1, ko = (s + 1) * BK;
                #pragma unroll
                for (int i = 0; i < 4; i++) {
                    cp16(sAw[nb][i], gA[i] + ko);
                    cp16(sBw[nb][i], gB[i] + (size_t)ko * N);
                }
                asm volatile("cp.async.commit_group;\n" ::: "memory");
            }

            const float* Ar = sA[s & 1] + ty * 8 * LDA;
            const float* Br = sB[s & 1] + tx * 4;

            #pragma unroll 8
            for (int k = 0; k < BK; k++) {
                float a[8];
                #pragma unroll
                for (int i = 0; i < 8; i++) a[i] = Ar[i * LDA + k];
                float b[8];
                *(float4*)(b)     = *(const float4*)(Br + k * LDB);
                *(float4*)(b + 4) = *(const float4*)(Br + k * LDB + 64);
                #pragma unroll
                for (int i = 0; i < 8; i++)
                    #pragma unroll
                    for (int j = 0; j < 8; j++)
                        acc[i][j] = fmaf(a[i], b[j], acc[i][j]);
            }
        }

        const int col0 = bn + tx * 4;
        const int col1 = bn + 64 + tx * 4;
        float4 bb0 = *(const float4*)(bias + col0);
        float4 bb1 = *(const float4*)(bias + col1);
        #pragma unroll
        for (int i = 0; i < 8; i++) {
            int row = bm + ty * 8 + i;
            float4 v0 = make_float4(acc[i][0] + bb0.x, acc[i][1] + bb0.y,
                                    acc[i][2] + bb0.z, acc[i][3] + bb0.w);
            float4 v1 = make_float4(acc[i][4] + bb1.x, acc[i][5] + bb1.y,
                                    acc[i][6] + bb1.z, acc[i][7] + bb1.w);
            if (act) {
                v0.x = rtf(gelu_tanh(v0.x)); v0.y = rtf(gelu_tanh(v0.y));
                v0.z = rtf(gelu_tanh(v0.z)); v0.w = rtf(gelu_tanh(v0.w));
                v1.x = rtf(gelu_tanh(v1.x)); v1.y = rtf(gelu_tanh(v1.y));
                v1.z = rtf(gelu_tanh(v1.z)); v1.w = rtf(gelu_tanh(v1.w));
            }
            *(float4*)(C + (size_t)row * N + col0) = v0;
            *(float4*)(C + (size_t)row * N + col1) = v1;
        }
    }
}

// mma fraction ~0.58 of column tiles
static inline int mma_tiles(int ntiles) {
    int m = (int)(ntiles * 0.58 + 0.5);
    if (m < 1) m = 1;
    if (m > ntiles) m = ntiles;
    return m;
}

// ---------------- RoPE (in-place on q and k slices of qkv) ----------------
__global__ __launch_bounds__(128) void rope_kernel(
    float* __restrict__ qkv, const float* __restrict__ coords,
    const float* __restrict__ inv_freq)
{
    int n = blockIdx.x;
    int t = threadIdx.x;
    __shared__ float cs[32], sn[32];
    if (t < 32) {
        float ang = coords[n * 4 + (t >> 3)] * inv_freq[t];
        cs[t] = cosf(ang);
        sn[t] = sinf(ang);
    }
    __syncthreads();
    for (int item = t; item < 1024; item += 128) {
        int i  = item & 31;
        int hs = item >> 5;
        int s  = hs & 1;
        int h  = hs >> 1;
        float* base = qkv + (size_t)n * QKV_N + s * EMBED + h * HDIM;
        float x1 = base[i], x2 = base[i + 32];
        float cc = cs[i], si = sn[i];
        base[i]      = x1 * cc - x2 * si;
        base[i + 32] = x2 * cc + x1 * si;
    }
}

// ---------------- varlen flash attention (fp32, online softmax, 2-key unroll) ----
__global__ __launch_bounds__(32) void attn_kernel(
    const float* __restrict__ qkv, const int* __restrict__ cu,
    const int* __restrict__ seg, float* __restrict__ out)
{
    const int lane = threadIdx.x;
    const int n = blockIdx.x * 32 + lane;
    const int h = blockIdx.y;

    float q[64];
    {
        const float4* qp = (const float4*)(qkv + (size_t)n * QKV_N + h * HDIM);
        #pragma unroll
        for (int i = 0; i < 16; i++) {
            float4 t = qp[i];
            q[4*i] = t.x; q[4*i+1] = t.y; q[4*i+2] = t.z; q[4*i+3] = t.w;
        }
    }

    const int s = seg[n];
    const int start = cu[s];
    const int end   = cu[s + 1];
    int jmin = start, jmax = end;
    #pragma unroll
    for (int off = 16; off; off >>= 1) {
        jmin = min(jmin, __shfl_xor_sync(0xffffffffu, jmin, off));
        jmax = max(jmax, __shfl_xor_sync(0xffffffffu, jmax, off));
    }

    float m = -1e30f, l = 0.f;
    float o[64];
    #pragma unroll
    for (int i = 0; i < 64; i++) o[i] = 0.f;

    int j = jmin;
    for (; j + 1 < jmax; j += 2) {
        const float4* kp0 = (const float4*)(qkv + (size_t)j       * QKV_N + EMBED + h * HDIM);
        const float4* kp1 = (const float4*)(qkv + (size_t)(j + 1) * QKV_N + EMBED + h * HDIM);
        float d0 = 0.f, d1 = 0.f;
        #pragma unroll
        for (int i = 0; i < 16; i++) {
            float4 t0 = kp0[i], t1 = kp1[i];
            d0 = fmaf(q[4*i],   t0.x, d0); d1 = fmaf(q[4*i],   t1.x, d1);
            d0 = fmaf(q[4*i+1], t0.y, d0); d1 = fmaf(q[4*i+1], t1.y, d1);
            d0 = fmaf(q[4*i+2], t0.z, d0); d1 = fmaf(q[4*i+2], t1.z, d1);
            d0 = fmaf(q[4*i+3], t0.w, d0); d1 = fmaf(q[4*i+3], t1.w, d1);
        }
        float s0 = (j     >= start && j     < end) ? d0 * 0.125f : -INFINITY;
        float s1 = (j + 1 >= start && j + 1 < end) ? d1 * 0.125f : -INFINITY;
        float mn = fmaxf(m, fmaxf(s0, s1));
        if (mn > m) {
            float sc = __expf(m - mn);
            l *= sc;
            #pragma unroll
            for (int i = 0; i < 64; i++) o[i] *= sc;
            m = mn;
        }
        float p0 = __expf(s0 - m);
        float p1 = __expf(s1 - m);
        l += p0 + p1;
        const float4* vp0 = (const float4*)(qkv + (size_t)j       * QKV_N + 2 * EMBED + h * HDIM);
        const float4* vp1 = (const float4*)(qkv + (size_t)(j + 1) * QKV_N + 2 * EMBED + h * HDIM);
        #pragma unroll
        for (int i = 0; i < 16; i++) {
            float4 t0 = vp0[i], t1 = vp1[i];
            o[4*i]   = fmaf(p0, t0.x, fmaf(p1, t1.x, o[4*i]));
            o[4*i+1] = fmaf(p0, t0.y, fmaf(p1, t1.y, o[4*i+1]));
            o[4*i+2] = fmaf(p0, t0.z, fmaf(p1, t1.z, o[4*i+2]));
            o[4*i+3] = fmaf(p0, t0.w, fmaf(p1, t1.w, o[4*i+3]));
        }
    }
    for (; j < jmax; j++) {
        const float4* kp = (const float4*)(qkv + (size_t)j * QKV_N + EMBED + h * HDIM);
        float d0 = 0.f;
        #pragma unroll
        for (int i = 0; i < 16; i++) {
            float4 t = kp[i];
            d0 = fmaf(q[4*i],   t.x, d0);
            d0 = fmaf(q[4*i+1], t.y, d0);
            d0 = fmaf(q[4*i+2], t.z, d0);
            d0 = fmaf(q[4*i+3], t.w, d0);
        }
        float s0 = (j >= start && j < end) ? d0 * 0.125f : -INFINITY;
        float mn = fmaxf(m, s0);
        if (mn > m) {
            float sc = __expf(m - mn);
            l *= sc;
            #pragma unroll
            for (int i = 0; i < 64; i++) o[i] *= sc;
            m = mn;
        }
        float p0 = __expf(s0 - m);
        l += p0;
        const float4* vp = (const float4*)(qkv + (size_t)j * QKV_N + 2 * EMBED + h * HDIM);
        #pragma unroll
        for (int i = 0; i < 16; i++) {
            float4 t = vp[i];
            o[4*i]   = fmaf(p0, t.x, o[4*i]);
            o[4*i+1] = fmaf(p0, t.y, o[4*i+1]);
            o[4*i+2] = fmaf(p0, t.z, o[4*i+2]);
            o[4*i+3] = fmaf(p0, t.w, o[4*i+3]);
        }
    }

    float inv = 1.f / l;
    float* op = out + (size_t)n * EMBED + h * HDIM;
    #pragma unroll
    for (int i = 0; i < 64; i += 4) {
        float4 t = make_float4(rtf(o[i] * inv), rtf(o[i+1] * inv),
                               rtf(o[i+2] * inv), rtf(o[i+3] * inv));
        *(float4*)(op + i) = t;
    }
}

// ---------------- fused residual-add + LayerNorm (optional tf32 rounding) ----------------
__global__ __launch_bounds__(256) void add_ln_kernel(
    const float* __restrict__ a, const float* __restrict__ b,
    const float* __restrict__ g, const float* __restrict__ beta,
    float* __restrict__ out, int roundout)
{
    const int n = blockIdx.x;
    const int t = threadIdx.x;
    __shared__ float red[8];
    __shared__ float bc;

    float x[4];
    float s = 0.f;
    #pragma unroll
    for (int i = 0; i < 4; i++) {
        int idx = t + i * 256;
        x[i] = a[(size_t)n * EMBED + idx] + b[(size_t)n * EMBED + idx];
        s += x[i];
    }
    #pragma unroll
    for (int off = 16; off; off >>= 1) s += __shfl_xor_sync(0xffffffffu, s, off);
    if ((t & 31) == 0) red[t >> 5] = s;
    __syncthreads();
    if (t < 8) {
        float v = red[t];
        #pragma unroll
        for (int off = 4; off; off >>= 1) v += __shfl_xor_sync(0xffu, v, off);
        if (t == 0) bc = v;
    }
    __syncthreads();
    float mean = bc * (1.0f / EMBED);
    __syncthreads();

    float var = 0.f;
    #pragma unroll
    for (int i = 0; i < 4; i++) {
        float d = x[i] - mean;
        var += d * d;
    }
    #pragma unroll
    for (int off = 16; off; off >>= 1) var += __shfl_xor_sync(0xffffffffu, var, off);
    if ((t & 31) == 0) red[t >> 5] = var;
    __syncthreads();
    if (t < 8) {
        float v = red[t];
        #pragma unroll
        for (int off = 4; off; off >>= 1) v += __shfl_xor_sync(0xffu, v, off);
        if (t == 0) bc = v;
    }
    __syncthreads();
    float rstd = rsqrtf(bc * (1.0f / EMBED) + 1e-5f);

    #pragma unroll
    for (int i = 0; i < 4; i++) {
        int idx = t + i * 256;
        float v = (x[i] - mean) * rstd * g[idx] + beta[idx];
        if (roundout) v = rtf(v);
        out[(size_t)n * EMBED + idx] = v;
    }
}

// ---------------- launch ----------------
extern "C" void kernel_launch(void* const* d_in, const int* in_sizes, int n_in,
                              void* d_out, int out_size)
{
    const float* coords  = (const float*)d_in[0];
    const float* feats   = (const float*)d_in[1];
    const int*   cu      = (const int*)  d_in[2];
    const float* Wqkv    = (const float*)d_in[3];
    const float* bqkv    = (const float*)d_in[4];
    const float* Wo      = (const float*)d_in[5];
    const float* bo      = (const float*)d_in[6];
    const float* inv_frq = (const float*)d_in[7];
    const float* ln1_g   = (const float*)d_in[8];
    const float* ln1_b   = (const float*)d_in[9];
    const float* W1      = (const float*)d_in[10];
    const float* b1      = (const float*)d_in[11];
    const float* W2      = (const float*)d_in[12];
    const float* b2      = (const float*)d_in[13];
    const float* ln2_g   = (const float*)d_in[14];
    const float* ln2_b   = (const float*)d_in[15];
    float* out = (float*)d_out;

    float *qkv, *attn, *tmp, *h, *ffn, *rfeats, *rwqkv, *rwo, *rw1, *rw2;
    int* seg;
    cudaGetSymbolAddress((void**)&qkv,    g_qkv);
    cudaGetSymbolAddress((void**)&attn,   g_attn);
    cudaGetSymbolAddress((void**)&tmp,    g_tmp);
    cudaGetSymbolAddress((void**)&h,      g_h);
    cudaGetSymbolAddress((void**)&ffn,    g_ffn);
    cudaGetSymbolAddress((void**)&rfeats, g_rfeats);
    cudaGetSymbolAddress((void**)&rwqkv,  g_rwqkv);
    cudaGetSymbolAddress((void**)&rwo,    g_rwo);
    cudaGetSymbolAddress((void**)&rw1,    g_rw1);
    cudaGetSymbolAddress((void**)&rw2,    g_rw2);
    cudaGetSymbolAddress((void**)&seg,    g_seg);

    cudaFuncSetAttribute(gemm_hybrid, cudaFuncAttributeMaxDynamicSharedMemorySize, TG_DSMEM);

    const int n4_feats = N_TOK * EMBED / 4;
    const int n4_wqkv  = EMBED * QKV_N / 4;
    const int n4_wo    = EMBED * EMBED / 4;
    const int n4_w1    = EMBED * FFN  / 4;
    const int n4_w2    = FFN  * EMBED / 4;

    const int t_qkv = QKV_N / BN, t_emb = EMBED / BN, t_ffn = FFN / BN;
    const int m_qkv = mma_tiles(t_qkv), m_emb = mma_tiles(t_emb), m_ffn = mma_tiles(t_ffn);

    // 0-2: prep
    seg_kernel<<<16, 256>>>(cu, seg);
    round_copy<<<RC_GRID(n4_feats), 256>>>((const float4*)feats, (float4*)rfeats, n4_feats);
    round_copy<<<RC_GRID(n4_wqkv),  256>>>((const float4*)Wqkv,  (float4*)rwqkv,  n4_wqkv);

    // 3: QKV projection  (ncu profiles launch index 3)
    gemm_hybrid<<<dim3(t_qkv, N_TOK / BM), 256, TG_DSMEM>>>(rfeats, rwqkv, bqkv, qkv,
                                                            QKV_N, EMBED, 0, m_qkv);
    // 4-6: remaining weight prep
    round_copy<<<RC_GRID(n4_wo), 256>>>((const float4*)Wo, (float4*)rwo, n4_wo);
    round_copy<<<RC_GRID(n4_w1), 256>>>((const float4*)W1, (float4*)rw1, n4_w1);
    round_copy<<<RC_GRID(n4_w2), 256>>>((const float4*)W2, (float4*)rw2, n4_w2);
    // 7: RoPE
    rope_kernel<<<N_TOK, 128>>>(qkv, coords, inv_frq);
    // 8: varlen attention (rounds its output)
    attn_kernel<<<dim3(N_TOK / 32, NHEADS), 32>>>(qkv, cu, seg, attn);
    // 9: output projection
    gemm_hybrid<<<dim3(t_emb, N_TOK / BM), 256, TG_DSMEM>>>(attn, rwo, bo, tmp,
                                                            EMBED, EMBED, 0, m_emb);
    // 10: h = LN1(feats + o)  (rounded: feeds FFN1)
    add_ln_kernel<<<N_TOK, 256>>>(feats, tmp, ln1_g, ln1_b, h, 1);
    // 11: FFN up + GELU (rounds output)
    gemm_hybrid<<<dim3(t_ffn, N_TOK / BM), 256, TG_DSMEM>>>(h, rw1, b1, ffn,
                                                            FFN, EMBED, 1, m_ffn);
    // 12: FFN down
    gemm_hybrid<<<dim3(t_emb, N_TOK / BM), 256, TG_DSMEM>>>(ffn, rw2, b2, tmp,
                                                            EMBED, FFN, 0, m_emb);
    // 13: out = LN2(h + f)  (full precision)
    add_ln_kernel<<<N_TOK, 256>>>(h, tmp, ln2_g, ln2_b, out, 0);
}

// round 11
// speedup vs baseline: 1.4080x; 1.4080x over previous
#include <cuda_runtime.h>
#include <cuda_bf16.h>
#include <cstdint>
#include <math.h>

// ---------------- problem constants ----------------
#define N_TOK   4096
#define EMBED   1024
#define NHEADS  16
#define HDIM    64
#define FFN     4096
#define QKV_N   3072

// ---------------- scratch (device globals; no allocation allowed) ----------------
__device__ float g_qkv   [N_TOK * QKV_N];
__device__ float g_attn  [N_TOK * EMBED];
__device__ float g_tmp   [N_TOK * EMBED];
__device__ float g_h     [N_TOK * EMBED];
__device__ float g_ffn   [N_TOK * FFN];
__device__ float g_rfeats[N_TOK * EMBED];
__device__ float g_rwqkv [EMBED * QKV_N];
__device__ float g_rwo   [EMBED * EMBED];
__device__ float g_rw1   [EMBED * FFN];
__device__ float g_rw2   [FFN * EMBED];
__device__ int   g_seg   [N_TOK];

// ---------------- small helpers ----------------
__device__ __forceinline__ unsigned f2tf(float x) {
    unsigned r;
    asm("cvt.rna.tf32.f32 %0, %1;" : "=r"(r) : "f"(x));
    return r;
}
__device__ __forceinline__ float rtf(float x) { return __uint_as_float(f2tf(x)); }

__device__ __forceinline__ void cp16(unsigned s, const void* g) {
    asm volatile("cp.async.cg.shared.global [%0], [%1], 16;\n" :: "r"(s), "l"(g));
}
__device__ __forceinline__ float gelu_tanh(float x) {
    float x3 = x * x * x;
    return 0.5f * x * (1.0f + tanhf(0.7978845608028654f * (x + 0.044715f * x3)));
}

// ---------------- segment ids ----------------
__global__ void seg_kernel(const int* __restrict__ cu, int* __restrict__ seg) {
    int n = blockIdx.x * blockDim.x + threadIdx.x;
    if (n < N_TOK) {
        int s = 0;
        #pragma unroll
        for (int j = 1; j <= 8; j++) s += (cu[j] <= n) ? 1 : 0;
        seg[n] = s;
    }
}

// ---------------- tf32-round copy ----------------
__global__ void round_copy(const float4* __restrict__ in, float4* __restrict__ out, int n4) {
    int i = blockIdx.x * blockDim.x + threadIdx.x;
    if (i < n4) {
        float4 v = in[i];
        v.x = rtf(v.x); v.y = rtf(v.y); v.z = rtf(v.z); v.w = rtf(v.w);
        out[i] = v;
    }
}
#define RC_GRID(n4) (((n4) + 255) / 256)

// ---------------- hybrid GEMM: C[M,N] = A[M,K] @ B[K,N] + bias (opt GELU) ------
// Column tiles [0, n_mma) use tf32 mma.sync (compat tensor unit);
// tiles [n_mma, ...) use fp32 FFMA SIMT on the SAME smem pipeline.
// A, B pre-rounded to tf32 -> products exact in fp32 -> both paths agree.
#define BM 128
#define BN 128
#define BK 32
#define LDA 36    // BK + 4
#define LDB 136   // BN + 8
#define ASTG (BM * LDA * 4)             // 18432 B
#define BSTG (BK * LDB * 4)             // 17408 B
#define STG  (ASTG + BSTG)              // 35840 B
#define TG_DSMEM (2 * STG)              // 71680 B

__global__ __launch_bounds__(256) void gemm_hybrid(
    const float* __restrict__ A, const float* __restrict__ B,
    const float* __restrict__ bias, float* __restrict__ C,
    int N, int K, int act, int n_mma)
{
    extern __shared__ float smem[];
    float* sA[2] = { smem,              smem + STG / 4 };
    float* sB[2] = { smem + ASTG / 4,   smem + (STG + ASTG) / 4 };

    const int tid  = threadIdx.x;
    const int bm   = blockIdx.y * BM;
    const int bn   = blockIdx.x * BN;

    // --- shared producer mapping (cp.async, 4x16B per thread per matrix) ---
    int aoff[4], boff[4];
    const float* gA[4];
    const float* gB[4];
    #pragma unroll
    for (int i = 0; i < 4; i++) {
        int ch = tid + i * 256;
        int ar = ch >> 3, ac = ch & 7;
        aoff[i] = ar * LDA + ac * 4;
        gA[i] = A + (size_t)(bm + ar) * K + ac * 4;
        int br = ch >> 5, bc2 = ch & 31;
        boff[i] = br * LDB + bc2 * 4;
        gB[i] = B + (size_t)br * N + bn + bc2 * 4;
    }
    unsigned sAw[2][4], sBw[2][4];
    #pragma unroll
    for (int b = 0; b < 2; b++)
        #pragma unroll
        for (int i = 0; i < 4; i++) {
            sAw[b][i] = (unsigned)__cvta_generic_to_shared(sA[b] + aoff[i]);
            sBw[b][i] = (unsigned)__cvta_generic_to_shared(sB[b] + boff[i]);
        }

    const int S = K / BK;
    #pragma unroll
    for (int i = 0; i < 4; i++) { cp16(sAw[0][i], gA[i]); cp16(sBw[0][i], gB[i]); }
    asm volatile("cp.async.commit_group;\n" ::: "memory");

    if (blockIdx.x < (unsigned)n_mma) {
        // ================= tensor (mma.sync tf32) path =================
        const int lane = tid & 31;
        const int warp = tid >> 5;
        const int g    = lane >> 2;
        const int c    = lane & 3;
        const int wm   = (warp >> 2) * 64;
        const int wn   = (warp & 3) * 32;

        float acc[4][4][4] = {};

        for (int s = 0; s < S; s++) {
            asm volatile("cp.async.wait_group 0;\n" ::: "memory");
            __syncthreads();
            if (s + 1 < S) {
                int nb = (s + 1) & 1, ko = (s + 1) * BK;
                #pragma unroll
                for (int i = 0; i < 4; i++) {
                    cp16(sAw[nb][i], gA[i] + ko);
                    cp16(sBw[nb][i], gB[i] + (size_t)ko * N);
                }
                asm volatile("cp.async.commit_group;\n" ::: "memory");
            }

            const float* Ar = sA[s & 1] + (wm + g) * LDA + c;
            const float* Br = sB[s & 1] + c * LDB + wn + g;

            #pragma unroll
            for (int kk = 0; kk < 4; kk++) {
                unsigned af[4][4];
                #pragma unroll
                for (int mt = 0; mt < 4; mt++) {
                    const float* p = Ar + mt * 16 * LDA + kk * 8;
                    af[mt][0] = __float_as_uint(p[0]);
                    af[mt][1] = __float_as_uint(p[8 * LDA]);
                    af[mt][2] = __float_as_uint(p[4]);
                    af[mt][3] = __float_as_uint(p[8 * LDA + 4]);
                }
                unsigned bf[4][2];
                #pragma unroll
                for (int nt = 0; nt < 4; nt++) {
                    const float* p = Br + kk * 8 * LDB + nt * 8;
                    bf[nt][0] = __float_as_uint(p[0]);
                    bf[nt][1] = __float_as_uint(p[4 * LDB]);
                }
                #pragma unroll
                for (int mt = 0; mt < 4; mt++)
                    #pragma unroll
                    for (int nt = 0; nt < 4; nt++)
                        asm volatile(
                            "mma.sync.aligned.m16n8k8.row.col.f32.tf32.tf32.f32 "
                            "{%0,%1,%2,%3}, {%4,%5,%6,%7}, {%8,%9}, {%0,%1,%2,%3};"
                            : "+f"(acc[mt][nt][0]), "+f"(acc[mt][nt][1]),
                              "+f"(acc[mt][nt][2]), "+f"(acc[mt][nt][3])
                            : "r"(af[mt][0]), "r"(af[mt][1]), "r"(af[mt][2]), "r"(af[mt][3]),
                              "r"(bf[nt][0]), "r"(bf[nt][1]));
            }
        }

        #pragma unroll
        for (int mt = 0; mt < 4; mt++) {
            int row0 = bm + wm + mt * 16 + g;
            #pragma unroll
            for (int nt = 0; nt < 4; nt++) {
                int col = bn + wn + nt * 8 + 2 * c;
                float b0 = bias[col], b1 = bias[col + 1];
                float2 v0 = make_float2(acc[mt][nt][0] + b0, acc[mt][nt][1] + b1);
                float2 v1 = make_float2(acc[mt][nt][2] + b0, acc[mt][nt][3] + b1);
                if (act) {
                    v0.x = rtf(gelu_tanh(v0.x)); v0.y = rtf(gelu_tanh(v0.y));
                    v1.x = rtf(gelu_tanh(v1.x)); v1.y = rtf(gelu_tanh(v1.y));
                }
                *(float2*)(C + (size_t)row0 * N + col)       = v0;
                *(float2*)(C + (size_t)(row0 + 8) * N + col) = v1;
            }
        }
    } else {
        // ================= SIMT (fp32 FFMA) path =================
        const int tx = tid & 15;     // column group
        const int ty = tid >> 4;     // row group (0..15)

        float acc[8][8] = {};

        for (int s = 0; s < S; s++) {
            asm volatile("cp.async.wait_group 0;\n" ::: "memory");
            __syncthreads();
            if (s + 1 < S) {
                int nb = (s + 1) & 1, ko = (s + 1) * BK;
                #pragma unroll
                for (int i = 0; i < 4; i++) {
                    cp16(sAw[nb][i], gA[i] + ko);
                    cp16(sBw[nb][i], gB[i] + (size_t)ko * N);
                }
                asm volatile("cp.async.commit_group;\n" ::: "memory");
            }

            const float* Ar = sA[s & 1] + ty * 8 * LDA;
            const float* Br = sB[s & 1] + tx * 4;

            #pragma unroll 8
            for (int k = 0; k < BK; k++) {
                float a[8];
                #pragma unroll
                for (int i = 0; i < 8; i++) a[i] = Ar[i * LDA + k];
                float b[8];
                *(float4*)(b)     = *(const float4*)(Br + k * LDB);
                *(float4*)(b + 4) = *(const float4*)(Br + k * LDB + 64);
                #pragma unroll
                for (int i = 0; i < 8; i++)
                    #pragma unroll
                    for (int j = 0; j < 8; j++)
                        acc[i][j] = fmaf(a[i], b[j], acc[i][j]);
            }
        }

        const int col0 = bn + tx * 4;
        const int col1 = bn + 64 + tx * 4;
        float4 bb0 = *(const float4*)(bias + col0);
        float4 bb1 = *(const float4*)(bias + col1);
        #pragma unroll
        for (int i = 0; i < 8; i++) {
            int row = bm + ty * 8 + i;
            float4 v0 = make_float4(acc[i][0] + bb0.x, acc[i][1] + bb0.y,
                                    acc[i][2] + bb0.z, acc[i][3] + bb0.w);
            float4 v1 = make_float4(acc[i][4] + bb1.x, acc[i][5] + bb1.y,
                                    acc[i][6] + bb1.z, acc[i][7] + bb1.w);
            if (act) {
                v0.x = rtf(gelu_tanh(v0.x)); v0.y = rtf(gelu_tanh(v0.y));
                v0.z = rtf(gelu_tanh(v0.z)); v0.w = rtf(gelu_tanh(v0.w));
                v1.x = rtf(gelu_tanh(v1.x)); v1.y = rtf(gelu_tanh(v1.y));
                v1.z = rtf(gelu_tanh(v1.z)); v1.w = rtf(gelu_tanh(v1.w));
            }
            *(float4*)(C + (size_t)row * N + col0) = v0;
            *(float4*)(C + (size_t)row * N + col1) = v1;
        }
    }
}

// mma fraction ~0.58 of column tiles
static inline int mma_tiles(int ntiles) {
    int m = (int)(ntiles * 0.58 + 0.5);
    if (m < 1) m = 1;
    if (m > ntiles) m = ntiles;
    return m;
}

// ---------------- RoPE (in-place on q and k slices of qkv) ----------------
__global__ __launch_bounds__(128) void rope_kernel(
    float* __restrict__ qkv, const float* __restrict__ coords,
    const float* __restrict__ inv_freq)
{
    int n = blockIdx.x;
    int t = threadIdx.x;
    __shared__ float cs[32], sn[32];
    if (t < 32) {
        float ang = coords[n * 4 + (t >> 3)] * inv_freq[t];
        cs[t] = cosf(ang);
        sn[t] = sinf(ang);
    }
    __syncthreads();
    for (int item = t; item < 1024; item += 128) {
        int i  = item & 31;
        int hs = item >> 5;
        int s  = hs & 1;
        int h  = hs >> 1;
        float* base = qkv + (size_t)n * QKV_N + s * EMBED + h * HDIM;
        float x1 = base[i], x2 = base[i + 32];
        float cc = cs[i], si = sn[i];
        base[i]      = x1 * cc - x2 * si;
        base[i + 32] = x2 * cc + x1 * si;
    }
}

// ---------------- varlen flash attention (fp32, online softmax) ----------------
// (R8-proven version: single-key loop, branch-skip of masked keys, no spills)
__global__ __launch_bounds__(32) void attn_kernel(
    const float* __restrict__ qkv, const int* __restrict__ cu,
    const int* __restrict__ seg, float* __restrict__ out)
{
    const int lane = threadIdx.x;
    const int n = blockIdx.x * 32 + lane;
    const int h = blockIdx.y;

    float q[64];
    {
        const float4* qp = (const float4*)(qkv + (size_t)n * QKV_N + h * HDIM);
        #pragma unroll
        for (int i = 0; i < 16; i++) {
            float4 t = qp[i];
            q[4*i] = t.x; q[4*i+1] = t.y; q[4*i+2] = t.z; q[4*i+3] = t.w;
        }
    }

    const int s = seg[n];
    const int start = cu[s];
    const int end   = cu[s + 1];
    int jmin = start, jmax = end;
    #pragma unroll
    for (int off = 16; off; off >>= 1) {
        jmin = min(jmin, __shfl_xor_sync(0xffffffffu, jmin, off));
        jmax = max(jmax, __shfl_xor_sync(0xffffffffu, jmax, off));
    }

    float m = -1e30f, l = 0.f;
    float o[64];
    #pragma unroll
    for (int i = 0; i < 64; i++) o[i] = 0.f;

    for (int j = jmin; j < jmax; j++) {
        const float4* kp = (const float4*)(qkv + (size_t)j * QKV_N + EMBED + h * HDIM);
        float dot = 0.f;
        #pragma unroll
        for (int i = 0; i < 16; i++) {
            float4 t = kp[i];
            dot = fmaf(q[4*i],   t.x, dot);
            dot = fmaf(q[4*i+1], t.y, dot);
            dot = fmaf(q[4*i+2], t.z, dot);
            dot = fmaf(q[4*i+3], t.w, dot);
        }
        dot *= 0.125f;
        if (j >= start && j < end) {
            if (dot > m) {
                float sc = __expf(m - dot);
                l *= sc;
                #pragma unroll
                for (int i = 0; i < 64; i++) o[i] *= sc;
                m = dot;
            }
            float p = __expf(dot - m);
            l += p;
            const float4* vp = (const float4*)(qkv + (size_t)j * QKV_N + 2 * EMBED + h * HDIM);
            #pragma unroll
            for (int i = 0; i < 16; i++) {
                float4 t = vp[i];
                o[4*i]   = fmaf(p, t.x, o[4*i]);
                o[4*i+1] = fmaf(p, t.y, o[4*i+1]);
                o[4*i+2] = fmaf(p, t.z, o[4*i+2]);
                o[4*i+3] = fmaf(p, t.w, o[4*i+3]);
            }
        }
    }

    float inv = 1.f / l;
    float* op = out + (size_t)n * EMBED + h * HDIM;
    #pragma unroll
    for (int i = 0; i < 64; i += 4) {
        // tf32-round: attention output is the A operand of the O-proj GEMM
        float4 t = make_float4(rtf(o[i] * inv), rtf(o[i+1] * inv),
                               rtf(o[i+2] * inv), rtf(o[i+3] * inv));
        *(float4*)(op + i) = t;
    }
}

// ---------------- fused residual-add + LayerNorm (optional tf32 rounding) ----------------
__global__ __launch_bounds__(256) void add_ln_kernel(
    const float* __restrict__ a, const float* __restrict__ b,
    const float* __restrict__ g, const float* __restrict__ beta,
    float* __restrict__ out, int roundout)
{
    const int n = blockIdx.x;
    const int t = threadIdx.x;
    __shared__ float red[8];
    __shared__ float bc;

    float x[4];
    float s = 0.f;
    #pragma unroll
    for (int i = 0; i < 4; i++) {
        int idx = t + i * 256;
        x[i] = a[(size_t)n * EMBED + idx] + b[(size_t)n * EMBED + idx];
        s += x[i];
    }
    #pragma unroll
    for (int off = 16; off; off >>= 1) s += __shfl_xor_sync(0xffffffffu, s, off);
    if ((t & 31) == 0) red[t >> 5] = s;
    __syncthreads();
    if (t < 8) {
        float v = red[t];
        #pragma unroll
        for (int off = 4; off; off >>= 1) v += __shfl_xor_sync(0xffu, v, off);
        if (t == 0) bc = v;
    }
    __syncthreads();
    float mean = bc * (1.0f / EMBED);
    __syncthreads();

    float var = 0.f;
    #pragma unroll
    for (int i = 0; i < 4; i++) {
        float d = x[i] - mean;
        var += d * d;
    }
    #pragma unroll
    for (int off = 16; off; off >>= 1) var += __shfl_xor_sync(0xffffffffu, var, off);
    if ((t & 31) == 0) red[t >> 5] = var;
    __syncthreads();
    if (t < 8) {
        float v = red[t];
        #pragma unroll
        for (int off = 4; off; off >>= 1) v += __shfl_xor_sync(0xffu, v, off);
        if (t == 0) bc = v;
    }
    __syncthreads();
    float rstd = rsqrtf(bc * (1.0f / EMBED) + 1e-5f);

    #pragma unroll
    for (int i = 0; i < 4; i++) {
        int idx = t + i * 256;
        float v = (x[i] - mean) * rstd * g[idx] + beta[idx];
        if (roundout) v = rtf(v);
        out[(size_t)n * EMBED + idx] = v;
    }
}

// ---------------- launch ----------------
extern "C" void kernel_launch(void* const* d_in, const int* in_sizes, int n_in,
                              void* d_out, int out_size)
{
    const float* coords  = (const float*)d_in[0];
    const float* feats   = (const float*)d_in[1];
    const int*   cu      = (const int*)  d_in[2];
    const float* Wqkv    = (const float*)d_in[3];
    const float* bqkv    = (const float*)d_in[4];
    const float* Wo      = (const float*)d_in[5];
    const float* bo      = (const float*)d_in[6];
    const float* inv_frq = (const float*)d_in[7];
    const float* ln1_g   = (const float*)d_in[8];
    const float* ln1_b   = (const float*)d_in[9];
    const float* W1      = (const float*)d_in[10];
    const float* b1      = (const float*)d_in[11];
    const float* W2      = (const float*)d_in[12];
    const float* b2      = (const float*)d_in[13];
    const float* ln2_g   = (const float*)d_in[14];
    const float* ln2_b   = (const float*)d_in[15];
    float* out = (float*)d_out;

    float *qkv, *attn, *tmp, *h, *ffn, *rfeats, *rwqkv, *rwo, *rw1, *rw2;
    int* seg;
    cudaGetSymbolAddress((void**)&qkv,    g_qkv);
    cudaGetSymbolAddress((void**)&attn,   g_attn);
    cudaGetSymbolAddress((void**)&tmp,    g_tmp);
    cudaGetSymbolAddress((void**)&h,      g_h);
    cudaGetSymbolAddress((void**)&ffn,    g_ffn);
    cudaGetSymbolAddress((void**)&rfeats, g_rfeats);
    cudaGetSymbolAddress((void**)&rwqkv,  g_rwqkv);
    cudaGetSymbolAddress((void**)&rwo,    g_rwo);
    cudaGetSymbolAddress((void**)&rw1,    g_rw1);
    cudaGetSymbolAddress((void**)&rw2,    g_rw2);
    cudaGetSymbolAddress((void**)&seg,    g_seg);

    cudaFuncSetAttribute(gemm_hybrid, cudaFuncAttributeMaxDynamicSharedMemorySize, TG_DSMEM);

    const int n4_feats = N_TOK * EMBED / 4;
    const int n4_wqkv  = EMBED * QKV_N / 4;
    const int n4_wo    = EMBED * EMBED / 4;
    const int n4_w1    = EMBED * FFN  / 4;
    const int n4_w2    = FFN  * EMBED / 4;

    const int t_qkv = QKV_N / BN, t_emb = EMBED / BN, t_ffn = FFN / BN;
    const int m_qkv = mma_tiles(t_qkv), m_emb = mma_tiles(t_emb), m_ffn = mma_tiles(t_ffn);

    // 0-2: prep
    seg_kernel<<<16, 256>>>(cu, seg);
    round_copy<<<RC_GRID(n4_feats), 256>>>((const float4*)feats, (float4*)rfeats, n4_feats);
    round_copy<<<RC_GRID(n4_wqkv),  256>>>((const float4*)Wqkv,  (float4*)rwqkv,  n4_wqkv);

    // 3: QKV projection  (ncu profiles launch index 3)
    gemm_hybrid<<<dim3(t_qkv, N_TOK / BM), 256, TG_DSMEM>>>(rfeats, rwqkv, bqkv, qkv,
                                                            QKV_N, EMBED, 0, m_qkv);
    // 4-6: remaining weight prep (overlaps GEMM on other SMs)
    round_copy<<<RC_GRID(n4_wo), 256>>>((const float4*)Wo, (float4*)rwo, n4_wo);
    round_copy<<<RC_GRID(n4_w1), 256>>>((const float4*)W1, (float4*)rw1, n4_w1);
    round_copy<<<RC_GRID(n4_w2), 256>>>((const float4*)W2, (float4*)rw2, n4_w2);
    // 7: RoPE
    rope_kernel<<<N_TOK, 128>>>(qkv, coords, inv_frq);
    // 8: varlen attention (rounds its output)
    attn_kernel<<<dim3(N_TOK / 32, NHEADS), 32>>>(qkv, cu, seg, attn);
    // 9: output projection
    gemm_hybrid<<<dim3(t_emb, N_TOK / BM), 256, TG_DSMEM>>>(attn, rwo, bo, tmp,
                                                            EMBED, EMBED, 0, m_emb);
    // 10: h = LN1(feats + o)  (rounded: feeds FFN1)
    add_ln_kernel<<<N_TOK, 256>>>(feats, tmp, ln1_g, ln1_b, h, 1);
    // 11: FFN up + GELU (rounds output)
    gemm_hybrid<<<dim3(t_ffn, N_TOK / BM), 256, TG_DSMEM>>>(h, rw1, b1, ffn,
                                                            FFN, EMBED, 1, m_ffn);
    // 12: FFN down
    gemm_hybrid<<<dim3(t_emb, N_TOK / BM), 256, TG_DSMEM>>>(ffn, rw2, b2, tmp,
                                                            EMBED, FFN, 0, m_emb);
    // 13: out = LN2(h + f)  (full precision)
    add_ln_kernel<<<N_TOK, 256>>>(h, tmp, ln2_g, ln2_b, out, 0);
}